// round 17
// baseline (speedup 1.0000x reference)
#include <cuda_runtime.h>
#include <cuda_bf16.h>
#include <cuda_fp16.h>
#include <math.h>

// Problem constants
#define NB 8
#define NL 1024
#define NC 1024
#define NH 16
#define ND 64
#define KW 512          // u32 (f16x2) per 1024-elem row

// Scratch (device globals — no allocation allowed)
__device__ float g_q[NB*NH*NL*ND];   // [B,H,L,D]
__device__ float g_k[NB*NH*NL*ND];
__device__ float g_v[NB*NH*NL*ND];
__device__ __align__(16) unsigned g_xh[NB*NL*KW];      // f16x2 hi(x)
__device__ __align__(16) unsigned g_xl[NB*NL*KW];      // f16x2 lo(x)
__device__ __align__(16) unsigned g_wq16[3*NC*KW];     // f16x2(w_qkv)
__device__ __align__(16) unsigned g_wp16[NC*KW];       // f16x2(w_proj)
__device__ __align__(16) unsigned g_aoh[NB*NL*KW];     // f16x2 hi(attn out)
__device__ __align__(16) unsigned g_aol[NB*NL*KW];     // f16x2 lo(attn out)
__device__ __align__(16) unsigned g_kf16[NB*NH*NL*ND/2]; // f16x2(K), [bh][l][d/2]
__device__ __align__(16) unsigned g_vt16[NB*NH*ND*NL/2]; // f16x2(V^T), [bh][d][l/2]

// ---------------- scalar/PTX helpers ----------------------------------------
static __device__ __forceinline__ void mma_fp16(float c[4], const unsigned a[4],
                                                const unsigned b[2]) {
    asm("mma.sync.aligned.m16n8k16.row.col.f32.f16.f16.f32 "
        "{%0,%1,%2,%3}, {%4,%5,%6,%7}, {%8,%9}, {%0,%1,%2,%3};"
        : "+f"(c[0]), "+f"(c[1]), "+f"(c[2]), "+f"(c[3])
        : "r"(a[0]), "r"(a[1]), "r"(a[2]), "r"(a[3]), "r"(b[0]), "r"(b[1]));
}
// pack two floats (x -> low half, y -> high half)
static __device__ __forceinline__ unsigned pk_f16(float x, float y) {
    unsigned r;
    asm("cvt.rn.f16x2.f32 %0, %1, %2;" : "=r"(r) : "f"(y), "f"(x));
    return r;
}
static __device__ __forceinline__ float f16_res(float x) {
    __half h = __float2half(x);
    return x - __half2float(h);
}
static __device__ __forceinline__ unsigned smem_u32(const void* p) {
    unsigned a;
    asm("{ .reg .u64 t; cvta.to.shared.u64 t, %1; cvt.u32.u64 %0, t; }"
        : "=r"(a) : "l"(p));
    return a;
}
static __device__ __forceinline__ void ldsm4(unsigned r[4], unsigned addr) {
    asm volatile("ldmatrix.sync.aligned.m8n8.x4.shared.b16 {%0,%1,%2,%3}, [%4];"
        : "=r"(r[0]), "=r"(r[1]), "=r"(r[2]), "=r"(r[3]) : "r"(addr));
}
static __device__ __forceinline__ void cpa16(unsigned dst, const void* src) {
    asm volatile("cp.async.cg.shared.global [%0], [%1], 16;"
                 :: "r"(dst), "l"(src) : "memory");
}
static __device__ __forceinline__ void cpa_commit() {
    asm volatile("cp.async.commit_group;" ::: "memory");
}
static __device__ __forceinline__ void cpa_wait0() {
    asm volatile("cp.async.wait_group 0;" ::: "memory");
}
static __device__ __forceinline__ void cpa_wait1() {
    asm volatile("cp.async.wait_group 1;" ::: "memory");
}

// ---------------- Prep: x -> f16 hi/lo planes; w_qkv/w_proj -> f16 ----------
__global__ void __launch_bounds__(256)
k_prep(const float4* __restrict__ x, const float4* __restrict__ wq,
       const float4* __restrict__ wp) {
    int i = blockIdx.x * blockDim.x + threadIdx.x;
    const int NX = NB*NL*NC/4;          // 2097152
    const int NW = 3*NC*NC/4;           // 786432
    const int NP = NC*NC/4;             // 262144
    if (i < NX) {
        float4 v = x[i];
        g_xh[2*i]     = pk_f16(v.x, v.y);
        g_xh[2*i + 1] = pk_f16(v.z, v.w);
        g_xl[2*i]     = pk_f16(f16_res(v.x), f16_res(v.y));
        g_xl[2*i + 1] = pk_f16(f16_res(v.z), f16_res(v.w));
    } else if (i < NX + NW) {
        int j = i - NX;
        float4 v = wq[j];
        g_wq16[2*j]     = pk_f16(v.x, v.y);
        g_wq16[2*j + 1] = pk_f16(v.z, v.w);
    } else if (i < NX + NW + NP) {
        int j = i - NX - NW;
        float4 v = wp[j];
        g_wp16[2*j]     = pk_f16(v.x, v.y);
        g_wp16[2*j + 1] = pk_f16(v.z, v.w);
    }
}

// ---------------- Prep: V -> f16x2 transposed [bh][d][l/2] ------------------
__global__ void __launch_bounds__(256)
k_prep_vt() {
    __shared__ float sm[64 * 65];
    const int bh = blockIdx.x >> 4;
    const int l0 = (blockIdx.x & 15) * 64;
    const int t = threadIdx.x;
    const float* vp = g_v + (size_t)bh * NL * ND + (size_t)l0 * ND;
    #pragma unroll
    for (int i = 0; i < 4; i++) {
        int idx = t + i * 256;          // 1024 float4: [64 l][16 f4]
        int l = idx >> 4, d4 = (idx & 15) * 4;
        float4 f = *(const float4*)(vp + (size_t)l * ND + d4);
        float* s = sm + l * 65 + d4;
        s[0] = f.x; s[1] = f.y; s[2] = f.z; s[3] = f.w;
    }
    __syncthreads();
    unsigned* out = g_vt16 + (size_t)bh * (ND * NL / 2) + (l0 >> 1);
    #pragma unroll
    for (int i = 0; i < 8; i++) {
        int idx = t + i * 256;          // 2048 u32: [64 d][32 p]
        int d = idx >> 5, p = idx & 31;
        out[(size_t)d * (NL / 2) + p] =
            pk_f16(sm[(2 * p) * 65 + d], sm[(2 * p + 1) * 65 + d]);
    }
}

// ---------------- fp16 asym-split NT GEMM, cp.async 3-stage -----------------
// C[128m x 128n] = (Ah+Al)[m,K] * B[n,K]^T.  B single fp16 (weights),
// A = hi/lo fp16 planes (near-fp32). 256 threads = 8 warps (4M x 2N).
// Row = 16 u32 (f16x2 of BK=32) + pad 4 -> pitch 20 (conflict-free LDSM).
#define GP2 20
#define PLW (128*GP2)               // 2560 words per plane per stage
#define STG3 (3*PLW)                // Ah,Al,B per stage
#define GEMM_SMEM (3 * STG3 * 4)    // 92160 B

__device__ __forceinline__ void gemm_f16(const unsigned* __restrict__ Ah,
                                         const unsigned* __restrict__ Al,
                                         const unsigned* __restrict__ Bw,
                                         int m0, int n0,
                                         unsigned* sm, float acc[2][8][4]) {
    const int tid  = threadIdx.x;
    const int lane = tid & 31, wid = tid >> 5;
    const int wm = (wid & 3) << 5;
    const int wn = (wid >> 2) << 6;

    const unsigned sbase = smem_u32(sm);
    const int l15 = lane & 15;
    const int lhi = (lane >> 4) * 16;
    const unsigned ahR = sbase + (unsigned)((wm + l15) * GP2) * 4 + lhi;
    const unsigned alR = ahR + PLW * 4;
    const unsigned bR  = sbase + (unsigned)(2 * PLW + (wn + l15) * GP2) * 4 + lhi;

    // loaders: 512 cpa16 per plane, 2 per thread: idx=tid+i*256, row=idx>>2, slot=idx&3
    const int NT = KW / 16;                  // 32 chunks of BK=32 (16 u32)

    // prologue: stages 0,1
    #pragma unroll
    for (int s = 0; s < 2; s++) {
        const unsigned off = s * (STG3 * 4);
        #pragma unroll
        for (int i = 0; i < 2; i++) {
            int idx = tid + i * 256;
            int row = idx >> 2, slot = idx & 3;
            unsigned d = off + (unsigned)(row * GP2 + slot * 4) * 4;
            const size_t gs = (size_t)slot * 4 + s * 16;
            cpa16(sbase + d,                 Ah + (size_t)(m0 + row) * KW + gs);
            cpa16(sbase + d + PLW * 4,       Al + (size_t)(m0 + row) * KW + gs);
            cpa16(sbase + d + 2 * PLW * 4,   Bw + (size_t)(n0 + row) * KW + gs);
        }
        cpa_commit();
    }

    int buf_w = 2;
    for (int kt = 0; kt < NT; kt++) {
        cpa_wait1();                        // stage kt resident
        __syncthreads();                    // all warps done with stage kt-1
        if (kt + 2 < NT) {
            const unsigned off = buf_w * (STG3 * 4);
            #pragma unroll
            for (int i = 0; i < 2; i++) {
                int idx = tid + i * 256;
                int row = idx >> 2, slot = idx & 3;
                unsigned d = off + (unsigned)(row * GP2 + slot * 4) * 4;
                const size_t gs = (size_t)slot * 4 + (size_t)(kt + 2) * 16;
                cpa16(sbase + d,               Ah + (size_t)(m0 + row) * KW + gs);
                cpa16(sbase + d + PLW * 4,     Al + (size_t)(m0 + row) * KW + gs);
                cpa16(sbase + d + 2 * PLW * 4, Bw + (size_t)(n0 + row) * KW + gs);
            }
        }
        cpa_commit();                       // always (group counting)
        if (++buf_w == 3) buf_w = 0;

        const unsigned boff = (unsigned)(kt % 3) * (STG3 * 4);
        #pragma unroll
        for (int ks = 0; ks < 2; ks++) {     // two k16 steps per BK=32
            const unsigned koff = boff + ks * 32;
            unsigned afh[2][4], afl[2][4];
            ldsm4(afh[0], ahR + koff);
            ldsm4(afh[1], ahR + koff + (16 * GP2 * 4));
            ldsm4(afl[0], alR + koff);
            ldsm4(afl[1], alR + koff + (16 * GP2 * 4));
            #pragma unroll
            for (int ntp = 0; ntp < 4; ntp++) {
                unsigned bq[4];
                ldsm4(bq, bR + koff + (unsigned)(ntp * 16 * GP2 * 4));
                unsigned b0[2] = { bq[0], bq[2] };
                unsigned b1[2] = { bq[1], bq[3] };
                #pragma unroll
                for (int mt = 0; mt < 2; mt++) {
                    mma_fp16(acc[mt][2 * ntp],     afh[mt], b0);
                    mma_fp16(acc[mt][2 * ntp],     afl[mt], b0);
                    mma_fp16(acc[mt][2 * ntp + 1], afh[mt], b1);
                    mma_fp16(acc[mt][2 * ntp + 1], afl[mt], b1);
                }
            }
        }
    }
}

// ---------------- Kernel 1: QKV GEMM + bias + scatter to [B,H,L,D] ----------
__global__ void __launch_bounds__(256)
k_qkv(const float* __restrict__ qb, const float* __restrict__ vb) {
    extern __shared__ unsigned smemu[];
    float acc[2][8][4];
    #pragma unroll
    for (int i = 0; i < 2; i++)
        #pragma unroll
        for (int j = 0; j < 8; j++)
            #pragma unroll
            for (int r = 0; r < 4; r++) acc[i][j][r] = 0.0f;

    const int n0 = blockIdx.x * 128;    // qkv channel base (weights on N side)
    const int m0 = blockIdx.y * 128;    // token base
    gemm_f16(g_xh, g_xl, g_wq16, m0, n0, smemu, acc);

    const int lane = threadIdx.x & 31, wid = threadIdx.x >> 5;
    const int wm = (wid & 3) << 5, wn = (wid >> 2) << 6;
    const int g = lane >> 2, tg = lane & 3;

    #pragma unroll
    for (int mt = 0; mt < 2; mt++) {
        #pragma unroll
        for (int half = 0; half < 2; half++) {
            int m  = m0 + wm + mt * 16 + g + half * 8;
            int bb = m >> 10;
            int l  = m & 1023;
            #pragma unroll
            for (int nt = 0; nt < 8; nt++) {
                int n     = n0 + wn + nt * 8 + 2 * tg;
                int which = n >> 10;           // 0=q 1=k 2=v
                int cc    = n & 1023;
                int h     = cc >> 6;
                int dd    = cc & 63;
                float2 r;
                r.x = acc[mt][nt][half * 2 + 0];
                r.y = acc[mt][nt][half * 2 + 1];
                float* dst;
                if (which == 0) {
                    float2 b2 = *(const float2*)(qb + cc);
                    r.x += b2.x; r.y += b2.y;
                    dst = g_q;
                } else if (which == 1) {
                    dst = g_k;
                } else {
                    float2 b2 = *(const float2*)(vb + cc);
                    r.x += b2.x; r.y += b2.y;
                    dst = g_v;
                }
                *(float2*)(dst + (((size_t)bb * NH + h) * NL + l) * ND + dd) = r;
            }
        }
    }
}

// ---------------- Kernel 2: L2 normalize; k rows emit f16x2 directly --------
__global__ void k_norm(const float* __restrict__ scale_mul) {
    const int lane = threadIdx.x & 31;
    const int row  = blockIdx.x * (blockDim.x >> 5) + (threadIdx.x >> 5);
    const int NQ   = NB * NH * NL;
    const bool isq = row < NQ;
    const int r    = isq ? row : row - NQ;
    float* base = (isq ? g_q : g_k) + (size_t)r * ND;
    float2 v = ((float2*)base)[lane];
    float ss = v.x * v.x + v.y * v.y;
    #pragma unroll
    for (int m = 16; m >= 1; m >>= 1)
        ss += __shfl_xor_sync(0xffffffffu, ss, m);
    float mul = 1.0f;
    if (isq) {
        int h = (r >> 10) & 15;
        mul = __expf(fminf(scale_mul[h], 4.605170185988091f)); // log(100)
    }
    float sc = mul / fmaxf(sqrtf(ss), 1e-12f);
    v.x *= sc; v.y *= sc;
    if (isq) {
        ((float2*)base)[lane] = v;          // q stays fp32 (attn Q frags)
    } else {
        g_kf16[(size_t)r * (ND / 2) + lane] = pk_f16(v.x, v.y);
    }
}

// ---------------- Kernel 3: flash attention (cp.async pipelined) ------------
// QK^T: fp16 m16n8k16, asymmetric split S = Qh.K + Ql.K.
// PV:   fp16 m16n8k16. K/V pre-converted fp16 in gmem -> pure cp.async tiles,
// double-buffered; bias cp.async into smem, hidden under QK MMAs.
#define KP 36                      // f16x2 K-tile pitch (uints per row)
#define VP 36                      // f16x2 V/P pitch (uints per row)
#define BP 68                      // bias tile pitch (floats per row)
// smem word offsets
#define OKF 0                      // 2 x 2304 (K double buffer)
#define OVH 4608                   // 2 x 2304 (V double buffer)
#define OBS 9216                   // 64*68 = 4352 (bias)
#define OPS 13568                  // 64*36 = 2304 (P)
#define ATTN_SMEM ((OPS + 2304) * 4)   // 63488 B

__global__ void __launch_bounds__(128, 3)
k_attn(const float* __restrict__ bias) {
    extern __shared__ unsigned smu[];
    unsigned* Ps = smu + OPS;

    const int t    = threadIdx.x;
    const int lane = t & 31, w = t >> 5;
    const int g = lane >> 2, tg = lane & 3;
    const int bh = blockIdx.y, h = bh & 15;
    const int q0 = blockIdx.x * 64;
    const int r0 = w * 16 + g;        // block-local q row (this thread: r0, r0+8)

    const unsigned sb = smem_u32(smu);
    // ldmatrix lane addressing (bytes)
    const int l15 = lane & 15;
    const int lhi = (lane >> 4) * 16;
    const unsigned kfR = sb + OKF * 4 + (unsigned)(l15 * KP) * 4 + lhi;
    const unsigned vhR = sb + OVH * 4 + (unsigned)(l15 * VP) * 4 + lhi;
    const unsigned psR = sb + OPS * 4 + (unsigned)((w * 16 + l15) * VP) * 4 + lhi;

    // cp.async loader addressing
    const int krow = t >> 3, kc = t & 7;
    const unsigned kDst = sb + OKF * 4 + (unsigned)(krow * KP + kc * 4) * 4;
    const unsigned vDst = sb + OVH * 4 + (unsigned)(krow * VP + kc * 4) * 4;
    const unsigned* kSrc = g_kf16 + (size_t)bh * (NL * ND / 2) + (size_t)krow * (ND / 2) + kc * 4;
    const unsigned* vSrc = g_vt16 + (size_t)bh * (ND * NL / 2) + (size_t)krow * (NL / 2) + kc * 4;
    const int brow = t >> 4, bc = t & 15;
    const unsigned bDst = sb + OBS * 4 + (unsigned)(brow * BP + bc * 4) * 4;
    const float* bSrc = bias + (size_t)h * NL * NL + (size_t)(q0 + brow) * NL + bc * 4;

    // Q fragments: f16x2 hi/lo
    unsigned qh[4][4], ql[4][4];
    {
        const float* qbase = g_q + ((size_t)bh * NL + q0) * ND;
        #pragma unroll
        for (int kg = 0; kg < 4; kg++) {
            #pragma unroll
            for (int i = 0; i < 4; i++) {
                int row = r0 + (i & 1) * 8;
                int kk  = kg * 16 + 2 * tg + (i >> 1) * 8;
                float x0 = qbase[(size_t)row * ND + kk];
                float x1 = qbase[(size_t)row * ND + kk + 1];
                qh[kg][i] = pk_f16(x0, x1);
                ql[kg][i] = pk_f16(f16_res(x0), f16_res(x1));
            }
        }
    }

    float o[8][4];
    #pragma unroll
    for (int nt = 0; nt < 8; nt++)
        #pragma unroll
        for (int i = 0; i < 4; i++) o[nt][i] = 0.0f;
    float m0 = -INFINITY, m1 = -INFINITY, l0 = 0.0f, l1 = 0.0f;

    // prologue: KV tile 0 -> buf 0
    #pragma unroll
    for (int i = 0; i < 4; i++) {
        cpa16(kDst + i * (16 * KP * 4), kSrc + (size_t)i * 16 * (ND / 2));
        cpa16(vDst + i * (16 * VP * 4), vSrc + (size_t)i * 16 * (NL / 2));
    }
    cpa_commit();

    for (int jt = 0; jt < 16; jt++) {
        const unsigned bufo = (unsigned)(jt & 1) * (2304 * 4);
        cpa_wait0();                  // KV tile jt resident
        __syncthreads();              // all warps done with prev buffers

        // issue bias jt (group 1), then KV jt+1 (group 2)
        #pragma unroll
        for (int i = 0; i < 8; i++)
            cpa16(bDst + i * (8 * BP * 4), bSrc + jt * 64 + (size_t)i * 8 * NL);
        cpa_commit();
        if (jt < 15) {
            const unsigned nbo = (unsigned)((jt + 1) & 1) * (2304 * 4);
            const unsigned* kS = kSrc + (size_t)(jt + 1) * 64 * (ND / 2);
            const unsigned* vS = vSrc + (jt + 1) * 32;
            #pragma unroll
            for (int i = 0; i < 4; i++) {
                cpa16(kDst + nbo + i * (16 * KP * 4), kS + (size_t)i * 16 * (ND / 2));
                cpa16(vDst + nbo + i * (16 * VP * 4), vS + (size_t)i * 16 * (NL / 2));
            }
        }
        cpa_commit();

        // S = Q K^T : fp16 k16, 2-term asymmetric split
        float s[8][4];
        #pragma unroll
        for (int nt = 0; nt < 8; nt++)
            #pragma unroll
            for (int i = 0; i < 4; i++) s[nt][i] = 0.0f;
        #pragma unroll
        for (int kg = 0; kg < 4; kg++) {
            #pragma unroll
            for (int ntp = 0; ntp < 4; ntp++) {
                unsigned hb[4];
                ldsm4(hb, kfR + bufo + (unsigned)(ntp * 16 * KP + kg * 8) * 4);
                unsigned h0[2] = { hb[0], hb[2] }, h1[2] = { hb[1], hb[3] };
                mma_fp16(s[2*ntp],     qh[kg], h0);
                mma_fp16(s[2*ntp],     ql[kg], h0);
                mma_fp16(s[2*ntp + 1], qh[kg], h1);
                mma_fp16(s[2*ntp + 1], ql[kg], h1);
            }
        }

        cpa_wait1();                  // bias jt resident (KV jt+1 may pend)
        __syncthreads();

        // bias add + tile max (bias from smem)
        const float* Bs = (const float*)(smu + OBS);
        float tm0 = -INFINITY, tm1 = -INFINITY;
        #pragma unroll
        for (int nt = 0; nt < 8; nt++) {
            int col = nt * 8 + 2 * tg;
            float2 b0 = *(const float2*)(Bs + r0 * BP + col);
            float2 b1 = *(const float2*)(Bs + (r0 + 8) * BP + col);
            s[nt][0] += b0.x; s[nt][1] += b0.y;
            s[nt][2] += b1.x; s[nt][3] += b1.y;
            tm0 = fmaxf(tm0, fmaxf(s[nt][0], s[nt][1]));
            tm1 = fmaxf(tm1, fmaxf(s[nt][2], s[nt][3]));
        }
        tm0 = fmaxf(tm0, __shfl_xor_sync(0xffffffffu, tm0, 1));
        tm0 = fmaxf(tm0, __shfl_xor_sync(0xffffffffu, tm0, 2));
        tm1 = fmaxf(tm1, __shfl_xor_sync(0xffffffffu, tm1, 1));
        tm1 = fmaxf(tm1, __shfl_xor_sync(0xffffffffu, tm1, 2));

        float mn0 = fmaxf(m0, tm0), mn1 = fmaxf(m1, tm1);
        float a0 = __expf(m0 - mn0), a1 = __expf(m1 - mn1);
        m0 = mn0; m1 = mn1;
        l0 *= a0; l1 *= a1;
        #pragma unroll
        for (int nt = 0; nt < 8; nt++) {
            o[nt][0] *= a0; o[nt][1] *= a0;
            o[nt][2] *= a1; o[nt][3] *= a1;
        }

        // p = exp(s - m); accumulate l; stage P into smem as f16x2
        #pragma unroll
        for (int nt = 0; nt < 8; nt++) {
            float p0 = __expf(s[nt][0] - m0), p1 = __expf(s[nt][1] - m0);
            float p2 = __expf(s[nt][2] - m1), p3 = __expf(s[nt][3] - m1);
            l0 += p0 + p1; l1 += p2 + p3;
            Ps[r0 * VP + nt * 4 + tg]       = pk_f16(p0, p1);
            Ps[(r0 + 8) * VP + nt * 4 + tg] = pk_f16(p2, p3);
        }
        __syncwarp();                  // Ps rows are warp-private

        // O += P V (fp16 k16)
        #pragma unroll
        for (int kg = 0; kg < 4; kg++) {
            unsigned ap4[4];
            ldsm4(ap4, psR + (unsigned)(kg * 32));
            #pragma unroll
            for (int ntp = 0; ntp < 4; ntp++) {
                unsigned bv4[4];
                ldsm4(bv4, vhR + bufo + (unsigned)(ntp * 16 * VP * 4) + kg * 32);
                unsigned v0[2] = { bv4[0], bv4[2] }, v1[2] = { bv4[1], bv4[3] };
                mma_fp16(o[2*ntp],     ap4, v0);
                mma_fp16(o[2*ntp + 1], ap4, v1);
            }
        }
    }

    // finish l reduction; write ao as f16 hi/lo planes (proj A operand)
    l0 += __shfl_xor_sync(0xffffffffu, l0, 1);
    l0 += __shfl_xor_sync(0xffffffffu, l0, 2);
    l1 += __shfl_xor_sync(0xffffffffu, l1, 1);
    l1 += __shfl_xor_sync(0xffffffffu, l1, 2);
    float i0 = 1.0f / l0, i1 = 1.0f / l1;

    size_t tok0 = (size_t)(bh >> 4) * NL + q0 + r0;
    unsigned* oph0 = g_aoh + tok0 * KW + h * (ND / 2);
    unsigned* opl0 = g_aol + tok0 * KW + h * (ND / 2);
    unsigned* oph1 = g_aoh + (tok0 + 8) * KW + h * (ND / 2);
    unsigned* opl1 = g_aol + (tok0 + 8) * KW + h * (ND / 2);
    #pragma unroll
    for (int nt = 0; nt < 8; nt++) {
        int cp = nt * 4 + tg;
        float f0 = o[nt][0] * i0, f1 = o[nt][1] * i0;
        float f2 = o[nt][2] * i1, f3 = o[nt][3] * i1;
        oph0[cp] = pk_f16(f0, f1);
        opl0[cp] = pk_f16(f16_res(f0), f16_res(f1));
        oph1[cp] = pk_f16(f2, f3);
        opl1[cp] = pk_f16(f16_res(f2), f16_res(f3));
    }
}

// ---------------- Kernel 4: output projection GEMM + bias -------------------
__global__ void __launch_bounds__(256)
k_proj(const float* __restrict__ bp, float* __restrict__ out) {
    extern __shared__ unsigned smemu[];
    float acc[2][8][4];
    #pragma unroll
    for (int i = 0; i < 2; i++)
        #pragma unroll
        for (int j = 0; j < 8; j++)
            #pragma unroll
            for (int r = 0; r < 4; r++) acc[i][j][r] = 0.0f;

    const int n0 = blockIdx.x * 128;
    const int m0 = blockIdx.y * 128;
    gemm_f16(g_aoh, g_aol, g_wp16, m0, n0, smemu, acc);

    const int lane = threadIdx.x & 31, wid = threadIdx.x >> 5;
    const int wm = (wid & 3) << 5, wn = (wid >> 2) << 6;
    const int g = lane >> 2, tg = lane & 3;

    #pragma unroll
    for (int mt = 0; mt < 2; mt++) {
        #pragma unroll
        for (int half = 0; half < 2; half++) {
            int m = m0 + wm + mt * 16 + g + half * 8;
            #pragma unroll
            for (int nt = 0; nt < 8; nt++) {
                int n = n0 + wn + nt * 8 + 2 * tg;
                float2 b2 = *(const float2*)(bp + n);
                float2 r;
                r.x = acc[mt][nt][half * 2 + 0] + b2.x;
                r.y = acc[mt][nt][half * 2 + 1] + b2.y;
                *(float2*)(out + (size_t)m * NC + n) = r;
            }
        }
    }
}

// ---------------- host launcher ---------------------------------------------
extern "C" void kernel_launch(void* const* d_in, const int* in_sizes, int n_in,
                              void* d_out, int out_size) {
    const float* x         = (const float*)d_in[0];
    const float* attn_bias = (const float*)d_in[1];
    const float* w_qkv     = (const float*)d_in[2];
    const float* q_bias    = (const float*)d_in[3];
    const float* v_bias    = (const float*)d_in[4];
    const float* scale_mul = (const float*)d_in[5];
    const float* w_proj    = (const float*)d_in[6];
    const float* b_proj    = (const float*)d_in[7];
    float* out = (float*)d_out;

    cudaFuncSetAttribute(k_qkv,  cudaFuncAttributeMaxDynamicSharedMemorySize, GEMM_SMEM);
    cudaFuncSetAttribute(k_proj, cudaFuncAttributeMaxDynamicSharedMemorySize, GEMM_SMEM);
    cudaFuncSetAttribute(k_attn, cudaFuncAttributeMaxDynamicSharedMemorySize, ATTN_SMEM);

    // x -> f16 hi/lo planes; w_qkv, w_proj -> f16
    k_prep<<<12288, 256>>>((const float4*)x, (const float4*)w_qkv,
                           (const float4*)w_proj);

    // QKV projection: fp16 asym-split GEMM, cp.async 3-stage
    k_qkv<<<dim3(24, 64), 256, GEMM_SMEM>>>(q_bias, v_bias);

    // L2-normalize q (fp32) and k (writes f16x2 K directly)
    k_norm<<<32768, 256>>>(scale_mul);

    // V -> f16x2 transposed [bh][d][l/2]
    k_prep_vt<<<2048, 256>>>();

    // attention: pipelined fp16 flash attention, 64-row q tiles
    k_attn<<<dim3(16, 128), 128, ATTN_SMEM>>>(attn_bias);

    // output projection: fp16 asym-split GEMM, cp.async 3-stage
    k_proj<<<dim3(8, 64), 256, GEMM_SMEM>>>(b_proj, out);
}